// round 6
// baseline (speedup 1.0000x reference)
#include <cuda_runtime.h>
#include <cuda_bf16.h>
#include <cstdint>

// ============================================================================
// PathwayPredictor, mma.sync bf16-split + ldmatrix, 2 molecules/CTA, 256 thr.
// GEMM1: X(embed, LDG frags) @ W1^T [K=80, 3-term]
// GEMM2: A(gmem-prefetched hi frags) @ H1(smem, ldmatrix) [K=64, 2-term]
// GEMM3: D2 (in-register chain) @ W2^T [K=80, 3-term]
// pool collapse: y = colsum(A) @ relu(D3+b2); head via __ldg(wp).
// ============================================================================

// smem float indices
#define B1I 0       // b1 padded [72]
#define B2I 72      // b2 padded [72]
#define BPI 144     // bp [16]
#define CSI 160     // csum [128] (mol-major)
#define PLI 288     // pool partials [8][72]
#define YI  864     // y [2][72]
#define ATI 1008    // atoms int [128]
// byte offsets
#define OFF_H 4608      // 2 x (72x72 hi + 72x72 lo) b16 = 41472
#define OFF_W 46080     // 72x88 hi + lo b16 = 25344 (W1 then W2)
#define SMEM_BYTES 71424
#define WTILE 12672     // one 72x88 bf16 tile, bytes
#define HTILE 20736     // per-mol H (hi+lo)
#define HHALF 10368

__device__ __align__(16) unsigned char g_wt[2][2][WTILE];  // [layer][hi/lo]

// ---------------- helpers ----------------
__device__ __forceinline__ void split2(float v, uint16_t& h, uint16_t& l) {
    __nv_bfloat16 bh = __float2bfloat16(v);
    h = *reinterpret_cast<uint16_t*>(&bh);
    __nv_bfloat16 bl = __float2bfloat16(v - __bfloat162float(bh));
    l = *reinterpret_cast<uint16_t*>(&bl);
}
__device__ __forceinline__ uint32_t packb(float2 v) {   // {hi:v.y, lo:v.x} bf16x2
    uint32_t r;
    asm("cvt.rn.satfinite.bf16x2.f32 %0, %1, %2;" : "=r"(r) : "f"(v.y), "f"(v.x));
    return r;
}
__device__ __forceinline__ void splitf2(float2 v, uint32_t& h, uint32_t& l) {
    h = packb(v);
    float hx = __uint_as_float(h << 16);
    float hy = __uint_as_float(h & 0xFFFF0000u);
    l = packb(make_float2(v.x - hx, v.y - hy));
}
__device__ __forceinline__ void mma16816(float c[4],
    uint32_t a0, uint32_t a1, uint32_t a2, uint32_t a3, uint32_t b0, uint32_t b1)
{
    asm volatile(
        "mma.sync.aligned.m16n8k16.row.col.f32.bf16.bf16.f32 "
        "{%0,%1,%2,%3},{%4,%5,%6,%7},{%8,%9},{%0,%1,%2,%3};"
        : "+f"(c[0]), "+f"(c[1]), "+f"(c[2]), "+f"(c[3])
        : "r"(a0), "r"(a1), "r"(a2), "r"(a3), "r"(b0), "r"(b1));
}
__device__ __forceinline__ void ldsm_x4(uint32_t& r0, uint32_t& r1,
                                        uint32_t& r2, uint32_t& r3, uint32_t a) {
    asm volatile("ldmatrix.sync.aligned.m8n8.x4.shared.b16 {%0,%1,%2,%3},[%4];"
        : "=r"(r0), "=r"(r1), "=r"(r2), "=r"(r3) : "r"(a));
}
__device__ __forceinline__ void ldsm_x2(uint32_t& r0, uint32_t& r1, uint32_t a) {
    asm volatile("ldmatrix.sync.aligned.m8n8.x2.shared.b16 {%0,%1},[%2];"
        : "=r"(r0), "=r"(r1) : "r"(a));
}

// One k16 step over 9 n-tiles. bhT/blT: per-thread x4 base addrs (hi/lo);
// b9h/b9l: per-thread x2 addrs for 9th tile. TERMS=3 adds the Alo*Bhi term.
template<int TERMS>
__device__ __forceinline__ void mma_tiles(
    uint32_t bhT, uint32_t blT, int pstride, uint32_t b9h, uint32_t b9l,
    const uint32_t ah[4], const uint32_t al[4], float C[9][4])
{
    #pragma unroll
    for (int p = 0; p < 4; p++) {
        uint32_t h0, h1, h2, h3, l0, l1, l2, l3;
        ldsm_x4(h0, h1, h2, h3, bhT + p * pstride);
        ldsm_x4(l0, l1, l2, l3, blT + p * pstride);
        mma16816(C[2*p],   ah[0], ah[1], ah[2], ah[3], h0, h1);
        mma16816(C[2*p],   ah[0], ah[1], ah[2], ah[3], l0, l1);
        if (TERMS == 3) mma16816(C[2*p], al[0], al[1], al[2], al[3], h0, h1);
        mma16816(C[2*p+1], ah[0], ah[1], ah[2], ah[3], h2, h3);
        mma16816(C[2*p+1], ah[0], ah[1], ah[2], ah[3], l2, l3);
        if (TERMS == 3) mma16816(C[2*p+1], al[0], al[1], al[2], al[3], h2, h3);
    }
    uint32_t h0, h1, l0, l1;
    ldsm_x2(h0, h1, b9h);
    ldsm_x2(l0, l1, b9l);
    mma16816(C[8], ah[0], ah[1], ah[2], ah[3], h0, h1);
    mma16816(C[8], ah[0], ah[1], ah[2], ah[3], l0, l1);
    if (TERMS == 3) mma16816(C[8], al[0], al[1], al[2], al[3], h0, h1);
}

// ---------------- weight prep: W^T split tiles [72 n][88 k] hi/lo ----------------
__global__ void prep_w(const float* __restrict__ w1, const float* __restrict__ w2) {
    int idx = blockIdx.x * 128 + threadIdx.x;
    if (idx >= 2 * 72 * 88) return;
    int l = idx / (72 * 88);
    int r = idx % (72 * 88);
    int n = r / 88, k = r % 88;
    const float* w = l ? w2 : w1;
    float v = (n < 70 && k < 70) ? w[k * 70 + n] : 0.f;
    uint16_t h, lo; split2(v, h, lo);
    *(uint16_t*)(g_wt[l][0] + r * 2) = h;
    *(uint16_t*)(g_wt[l][1] + r * 2) = lo;
}

// ---------------- main kernel ----------------
__global__ __launch_bounds__(256, 2)
void pathway_mma3(const int* __restrict__ atoms, const float* __restrict__ adj,
                  const float* __restrict__ sel, const float* __restrict__ emb,
                  const float* __restrict__ b1, const float* __restrict__ b2,
                  const float* __restrict__ wp, const float* __restrict__ bp,
                  float* __restrict__ out)
{
    extern __shared__ __align__(16) unsigned char sm[];
    float* smf = (float*)sm;
    int*   smi = (int*)sm;
    uint32_t sb;
    asm("{ .reg .u64 t; cvta.to.shared.u64 t, %1; cvt.u32.u64 %0, t; }"
        : "=r"(sb) : "l"(sm));
    const int t = threadIdx.x, lane = t & 31, wid = t >> 5;
    const int bid = blockIdx.x;
    const int q = lane >> 2, qp = lane & 3;
    const int mol = wid >> 2;
    const int mrow = wid * 16;
    const int mloc = mrow & 63;

    // per-thread ldmatrix bases
    const int rin  = (lane & 7) + ((lane >> 4) << 3);
    const int ksel = (lane >> 3) & 1;
    const int l15  = lane & 15, rin9 = l15 & 7, ksel9 = l15 >> 3;
    const uint32_t sW  = sb + OFF_W;
    const uint32_t wH  = sW + (uint32_t)(rin * 88 + ksel * 8) * 2;
    const uint32_t wL  = wH + WTILE;
    const uint32_t w9H = sW + (uint32_t)((64 + rin9) * 88 + ksel9 * 8) * 2;
    const uint32_t w9L = w9H + WTILE;
    const uint32_t sH  = sb + OFF_H + (uint32_t)mol * HTILE;
    const uint32_t hHa = sH + (uint32_t)(rin * 72 + ksel * 8) * 2;
    const uint32_t hLa = hHa + HHALF;
    const uint32_t h9H = sH + (uint32_t)((64 + rin9) * 72 + ksel9 * 8) * 2;
    const uint32_t h9L = h9H + HHALF;
    uint16_t* H16h = (uint16_t*)(sm + OFF_H + mol * HTILE);
    uint16_t* H16l = H16h + 72 * 72;

    // ================= phase 0 =================
    {   // W1 split tiles -> smem
        const uint4* gw = (const uint4*)g_wt[0][0];
        uint4* sw = (uint4*)(sm + OFF_W);
        #pragma unroll
        for (int i = t; i < 2 * WTILE / 16; i += 256) sw[i] = gw[i];
    }
    if (t < 128) smi[ATI + t] = atoms[(size_t)bid * 128 + t];
    if (t < 72) { smf[B1I + t] = (t < 70) ? b1[t] : 0.f;
                  smf[B2I + t] = (t < 70) ? b2[t] : 0.f; }
    if (t < 11) smf[BPI + t] = bp[t];
    if (t < 128) {   // colsum from gmem (coalesced per n), warms L2 for A
        const float* cb = adj + ((size_t)(2 * bid) + (t >> 6)) * 4096 + (t & 63);
        float s = 0.f;
        #pragma unroll 8
        for (int n = 0; n < 64; n++) s += cb[n * 64];
        smf[CSI + t] = s;
    }
    // prefetch GEMM2 A-fragments (hi only; 2-term GEMM2 needs no A-lo)
    uint32_t ahA[4][4];
    {
        const float2* r0p = (const float2*)(adj + ((size_t)(2 * bid) + mol) * 4096
                                            + (size_t)(mloc + q) * 64);
        const float2* r1p = r0p + 256;   // +8 rows
        #pragma unroll
        for (int ks = 0; ks < 4; ks++) {
            ahA[ks][0] = packb(r0p[8 * ks + qp]);
            ahA[ks][1] = packb(r1p[8 * ks + qp]);
            ahA[ks][2] = packb(r0p[8 * ks + qp + 4]);
            ahA[ks][3] = packb(r1p[8 * ks + qp + 4]);
        }
    }
    __syncthreads();

    float C[9][4];
    #pragma unroll
    for (int n = 0; n < 9; n++)
        #pragma unroll
        for (int i = 0; i < 4; i++) C[n][i] = 0.f;

    // ================= GEMM1: D1 = X @ W1^T (K=80, 3-term) =================
    {
        const int a0i = smi[ATI + mrow + q];
        const int a1i = smi[ATI + mrow + q + 8];
        const float2* e0 = (const float2*)(emb + (size_t)a0i * 70);
        const float2* e1 = (const float2*)(emb + (size_t)a1i * 70);
        float2 v[5][4];
        const float2 z2 = make_float2(0.f, 0.f);
        #pragma unroll
        for (int ks = 0; ks < 5; ks++) {
            const int k0 = 16 * ks + 2 * qp, k1 = k0 + 8;
            v[ks][0] = (k0 < 70) ? e0[k0 >> 1] : z2;
            v[ks][1] = (k0 < 70) ? e1[k0 >> 1] : z2;
            v[ks][2] = (k1 < 70) ? e0[k1 >> 1] : z2;
            v[ks][3] = (k1 < 70) ? e1[k1 >> 1] : z2;
        }
        #pragma unroll
        for (int ks = 0; ks < 5; ks++) {
            uint32_t ah[4], al[4];
            splitf2(v[ks][0], ah[0], al[0]);
            splitf2(v[ks][1], ah[1], al[1]);
            splitf2(v[ks][2], ah[2], al[2]);
            splitf2(v[ks][3], ah[3], al[3]);
            mma_tiles<3>(wH + ks * 32, wL + ks * 32, 2816,
                         w9H + ks * 32, w9L + ks * 32, ah, al, C);
        }
    }

    // ---- epi1: H1 = relu(D1+b1) -> H^T hi/lo ----
    {
        const int r0 = mloc + q, r1 = r0 + 8;
        #pragma unroll
        for (int n = 0; n < 9; n++) {
            const int d0 = n * 8 + qp * 2;
            float h00 = fmaxf(C[n][0] + smf[B1I + d0], 0.f);
            float h01 = fmaxf(C[n][1] + smf[B1I + d0 + 1], 0.f);
            float h10 = fmaxf(C[n][2] + smf[B1I + d0], 0.f);
            float h11 = fmaxf(C[n][3] + smf[B1I + d0 + 1], 0.f);
            uint16_t hh, hl;
            split2(h00, hh, hl); H16h[d0 * 72 + r0] = hh;       H16l[d0 * 72 + r0] = hl;
            split2(h01, hh, hl); H16h[(d0 + 1) * 72 + r0] = hh; H16l[(d0 + 1) * 72 + r0] = hl;
            split2(h10, hh, hl); H16h[d0 * 72 + r1] = hh;       H16l[d0 * 72 + r1] = hl;
            split2(h11, hh, hl); H16h[(d0 + 1) * 72 + r1] = hh; H16l[(d0 + 1) * 72 + r1] = hl;
        }
    }
    __syncthreads();   // H ready; W1 fully consumed

    {   // W2 split tiles over W1 (completes before next sync)
        const uint4* gw = (const uint4*)g_wt[1][0];
        uint4* sw = (uint4*)(sm + OFF_W);
        #pragma unroll
        for (int i = t; i < 2 * WTILE / 16; i += 256) sw[i] = gw[i];
    }

    // ================= GEMM2: D2 = A @ H1 (K=64, 2-term, A-hi regs) ========
    #pragma unroll
    for (int n = 0; n < 9; n++)
        #pragma unroll
        for (int i = 0; i < 4; i++) C[n][i] = 0.f;
    #pragma unroll
    for (int ks = 0; ks < 4; ks++)
        mma_tiles<2>(hHa + ks * 32, hLa + ks * 32, 2304,
                     h9H + ks * 32, h9L + ks * 32, ahA[ks], ahA[ks], C);
    __syncthreads();   // W2 stores complete

    // ================= GEMM3: D3 = D2 @ W2^T (chained, K=80, 3-term) =======
    float C3[9][4];
    #pragma unroll
    for (int n = 0; n < 9; n++)
        #pragma unroll
        for (int i = 0; i < 4; i++) C3[n][i] = 0.f;
    #pragma unroll
    for (int ks = 0; ks < 5; ks++) {
        uint32_t ah[4], al[4];
        splitf2(make_float2(C[2*ks][0], C[2*ks][1]), ah[0], al[0]);
        splitf2(make_float2(C[2*ks][2], C[2*ks][3]), ah[1], al[1]);
        if (ks < 4) {
            splitf2(make_float2(C[2*ks+1][0], C[2*ks+1][1]), ah[2], al[2]);
            splitf2(make_float2(C[2*ks+1][2], C[2*ks+1][3]), ah[3], al[3]);
        } else { ah[2] = al[2] = ah[3] = al[3] = 0u; }
        mma_tiles<3>(wH + ks * 32, wL + ks * 32, 2816,
                     w9H + ks * 32, w9L + ks * 32, ah, al, C3);
    }

    // ---- epi3: pool partials ----
    {
        const float cs0 = smf[CSI + mrow + q];
        const float cs1 = smf[CSI + mrow + q + 8];
        #pragma unroll
        for (int n = 0; n < 9; n++) {
            #pragma unroll
            for (int j = 0; j < 2; j++) {
                const int d = n * 8 + qp * 2 + j;
                float v = cs0 * fmaxf(C3[n][j] + smf[B2I + d], 0.f)
                        + cs1 * fmaxf(C3[n][2 + j] + smf[B2I + d], 0.f);
                v += __shfl_xor_sync(0xFFFFFFFFu, v, 4);
                v += __shfl_xor_sync(0xFFFFFFFFu, v, 8);
                v += __shfl_xor_sync(0xFFFFFFFFu, v, 16);
                if (q == 0) smf[PLI + wid * 72 + d] = v;
            }
        }
    }
    __syncthreads();

    if (t < 144) {
        const int mY = t / 72, d = t - mY * 72;
        float y = smf[PLI + (mY * 4 + 0) * 72 + d] + smf[PLI + (mY * 4 + 1) * 72 + d]
                + smf[PLI + (mY * 4 + 2) * 72 + d] + smf[PLI + (mY * 4 + 3) * 72 + d];
        smf[YI + t] = y;
    }
    __syncthreads();

    if (t < 22) {
        const int mH = t / 11, c = t - mH * 11;
        float s = smf[BPI + c];
        #pragma unroll 7
        for (int d = 0; d < 70; d++)
            s += smf[YI + mH * 72 + d] * __ldg(&wp[d * 11 + c]);
        const float* sv = sel + (size_t)(2 * bid + mH) * 7;
        #pragma unroll
        for (int e = 0; e < 7; e++)
            s += __ldg(&sv[e]) * __ldg(&wp[(70 + e) * 11 + c]);
        out[(size_t)(2 * bid + mH) * 11 + c] = s;
    }
}

extern "C" void kernel_launch(void* const* d_in, const int* in_sizes, int n_in,
                              void* d_out, int out_size)
{
    const int*   atoms = (const int*)  d_in[0];
    const float* adj   = (const float*)d_in[1];
    const float* sel   = (const float*)d_in[2];
    const float* emb   = (const float*)d_in[3];
    const float* w1    = (const float*)d_in[4];
    const float* b1    = (const float*)d_in[5];
    const float* w2    = (const float*)d_in[6];
    const float* b2    = (const float*)d_in[7];
    const float* wp    = (const float*)d_in[8];
    const float* bp    = (const float*)d_in[9];
    float* out = (float*)d_out;

    prep_w<<<(2 * 72 * 88 + 127) / 128, 128>>>(w1, w2);

    cudaFuncSetAttribute(pathway_mma3,
                         cudaFuncAttributeMaxDynamicSharedMemorySize, SMEM_BYTES);
    pathway_mma3<<<4096, 256, SMEM_BYTES>>>(atoms, adj, sel, emb,
                                            b1, b2, wp, bp, out);
}

// round 8
// speedup vs baseline: 1.2614x; 1.2614x over previous
#include <cuda_runtime.h>
#include <cuda_bf16.h>
#include <cstdint>

// ============================================================================
// PathwayPredictor, mma.sync bf16-split, 2 molecules/CTA, 256 threads.
// GEMM1: X(embed, direct-LDG frags) @ W1^T   [K=80, 3-term]
// GEMM2: A(split hi, smem) @ H1(smem)        [K=64, 2-term]
// GEMM3: D2(in-register chain) @ W2^T        [K=80, 3-term]
// pool collapse: y = colsum(A) @ relu(D3+b2); tiny head.
// ============================================================================

#define SWW 44   // W row stride, u32 words (88 bf16)
#define SHW 36   // H / Asplit row stride, u32 words (72 bf16)
#define SSTG 66  // fp32 staging row stride (EVEN -> float2-aligned)

// smem float indices
#define B1I 0       // b1 padded [72]
#define B2I 72      // b2 padded [72]
#define BPI 144     // bp [16]
#define CSI 160     // csum [128]  (mol-major)
#define PLI 288     // pool partials [8][72]
#define YI  864     // y [2][72]
// byte offsets
#define OFF_H 7936      // 2 x (72x72 hi + 72x72 lo) b16 = 41472 ; ALIASES A fp32 staging [2][64][66]
#define OFF_W 49408     // 72x88 hi + lo b16 = 25344 (W1 then W2)
#define OFF_A 74752     // 2 x (64x72 hi) b16 = 18432
#define SMEM_BYTES 93184
#define WTILE 12672
#define HTILE 20736
#define ATILE 9216

__device__ __align__(16) unsigned char g_wt[2][2][WTILE];  // [layer][hi/lo]

// ---------------- helpers ----------------
__device__ __forceinline__ void split2(float v, uint16_t& h, uint16_t& l) {
    __nv_bfloat16 bh = __float2bfloat16(v);
    h = *reinterpret_cast<uint16_t*>(&bh);
    __nv_bfloat16 bl = __float2bfloat16(v - __bfloat162float(bh));
    l = *reinterpret_cast<uint16_t*>(&bl);
}
__device__ __forceinline__ uint32_t packb(float2 v) {   // word: lo16=bf16(v.x), hi16=bf16(v.y)
    uint32_t r;
    asm("cvt.rn.satfinite.bf16x2.f32 %0, %1, %2;" : "=r"(r) : "f"(v.y), "f"(v.x));
    return r;
}
__device__ __forceinline__ void splitf2(float2 v, uint32_t& h, uint32_t& l) {
    h = packb(v);
    float hx = __uint_as_float(h << 16);
    float hy = __uint_as_float(h & 0xFFFF0000u);
    l = packb(make_float2(v.x - hx, v.y - hy));
}
__device__ __forceinline__ void mma16816(float c[4],
    uint32_t a0, uint32_t a1, uint32_t a2, uint32_t a3, uint32_t b0, uint32_t b1)
{
    asm volatile(
        "mma.sync.aligned.m16n8k16.row.col.f32.bf16.bf16.f32 "
        "{%0,%1,%2,%3},{%4,%5,%6,%7},{%8,%9},{%0,%1,%2,%3};"
        : "+f"(c[0]), "+f"(c[1]), "+f"(c[2]), "+f"(c[3])
        : "r"(a0), "r"(a1), "r"(a2), "r"(a3), "r"(b0), "r"(b1));
}

// 9 n-tiles, one k16 step: B hi/lo frags from smem (scalar LDS, compiler hoists).
// TERMS==3 adds the Alo*Bhi term.
template<int TERMS>
__device__ __forceinline__ void mma_n9(
    const uint32_t* __restrict__ Bhi, const uint32_t* __restrict__ Blo,
    int rbase, int sb, int q,
    const uint32_t ah[4], const uint32_t al[4], float C[9][4])
{
    #pragma unroll
    for (int n = 0; n < 9; n++) {
        const int rb = (n * 8 + q) * sb + rbase;
        uint32_t bh0 = Bhi[rb], bh1 = Bhi[rb + 4];
        uint32_t bl0 = Blo[rb], bl1 = Blo[rb + 4];
        mma16816(C[n], ah[0], ah[1], ah[2], ah[3], bh0, bh1);
        mma16816(C[n], ah[0], ah[1], ah[2], ah[3], bl0, bl1);
        if (TERMS == 3) mma16816(C[n], al[0], al[1], al[2], al[3], bh0, bh1);
    }
}

// ---------------- weight prep: W^T split tiles [72 n][88 k] hi/lo ----------------
__global__ void prep_w(const float* __restrict__ w1, const float* __restrict__ w2) {
    int idx = blockIdx.x * 128 + threadIdx.x;
    if (idx >= 2 * 72 * 88) return;
    int l = idx / (72 * 88);
    int r = idx % (72 * 88);
    int n = r / 88, k = r % 88;
    const float* w = l ? w2 : w1;
    float v = (n < 70 && k < 70) ? w[k * 70 + n] : 0.f;
    uint16_t h, lo; split2(v, h, lo);
    *(uint16_t*)(g_wt[l][0] + r * 2) = h;
    *(uint16_t*)(g_wt[l][1] + r * 2) = lo;
}

// ---------------- main kernel ----------------
__global__ __launch_bounds__(256, 2)
void pathway_mma4(const int* __restrict__ atoms, const float* __restrict__ adj,
                  const float* __restrict__ sel, const float* __restrict__ emb,
                  const float* __restrict__ b1, const float* __restrict__ b2,
                  const float* __restrict__ wp, const float* __restrict__ bp,
                  float* __restrict__ out)
{
    extern __shared__ __align__(16) unsigned char sm[];
    float* smf = (float*)sm;
    const int t = threadIdx.x, lane = t & 31, wid = t >> 5;
    const int bid = blockIdx.x;
    const int q = lane >> 2, qp = lane & 3;
    const int mol = wid >> 2;                 // molecule 0/1
    const int mrow = wid * 16;                // global row 0..112
    const int mloc = mrow & 63;               // row within molecule

    uint32_t* Whi = (uint32_t*)(sm + OFF_W);  uint32_t* Wlo = Whi + 72 * SWW;
    uint32_t* Hhi = (uint32_t*)(sm + OFF_H + mol * HTILE);
    uint32_t* Hlo = Hhi + 72 * SHW;
    uint16_t* H16h = (uint16_t*)(sm + OFF_H + mol * HTILE);
    uint16_t* H16l = H16h + 72 * 72;
    uint32_t* Ahi = (uint32_t*)(sm + OFF_A + mol * ATILE);
    float* stg = smf + OFF_H / 4;             // [2][64][66] fp32, aliases H (dead before epi1)

    // ================= phase 0: loads =================
    {   // adjacency fp32 -> staging, coalesced
        const float* Ab = adj + (size_t)bid * 8192;
        #pragma unroll
        for (int i = t; i < 8192; i += 256) {
            int m2 = i >> 12, ii = i & 4095;
            stg[m2 * 64 * SSTG + (ii >> 6) * SSTG + (ii & 63)] = Ab[i];
        }
    }
    {   // W1 split tiles
        const uint4* gw = (const uint4*)g_wt[0][0];
        uint4* sw = (uint4*)(sm + OFF_W);
        #pragma unroll
        for (int i = t; i < 2 * WTILE / 16; i += 256) sw[i] = gw[i];
    }
    if (t < 72) { smf[B1I + t] = (t < 70) ? b1[t] : 0.f;
                  smf[B2I + t] = (t < 70) ? b2[t] : 0.f; }
    if (t < 11) smf[BPI + t] = bp[t];
    __syncthreads();

    // ================= phase 1: colsum + A split (hi only) =================
    if (t < 128) {
        const float* cb = stg + (t >> 6) * 64 * SSTG + (t & 63);
        float s = 0.f;
        #pragma unroll 8
        for (int n = 0; n < 64; n++) s += cb[n * SSTG];
        smf[CSI + t] = s;
    }
    {   // split A rows: thread -> (molA, row n, half); packed bf16-hi words
        const int molA = t >> 7, n = (t >> 1) & 63, half = t & 1;
        const float2* ar = (const float2*)(stg + molA * 64 * SSTG + n * SSTG + half * 32);
        uint32_t* ah = (uint32_t*)(sm + OFF_A + molA * ATILE) + n * SHW + half * 16;
        #pragma unroll
        for (int j = 0; j < 16; j++) ah[j] = packb(ar[j]);
    }
    __syncthreads();   // staging dead from here (H may be written)

    float C[9][4];
    #pragma unroll
    for (int n = 0; n < 9; n++)
        #pragma unroll
        for (int i = 0; i < 4; i++) C[n][i] = 0.f;

    // ================= GEMM1: D1 = X @ W1^T  (K=80, X frags via LDG) ========
    {
        const int a0i = __ldg(&atoms[(size_t)bid * 128 + mrow + q]);
        const int a1i = __ldg(&atoms[(size_t)bid * 128 + mrow + q + 8]);
        const float2* e0 = (const float2*)(emb + (size_t)a0i * 70);
        const float2* e1 = (const float2*)(emb + (size_t)a1i * 70);
        float2 v[5][4];
        const float2 z2 = make_float2(0.f, 0.f);
        #pragma unroll
        for (int ks = 0; ks < 5; ks++) {
            const int k0 = 16 * ks + 2 * qp, k1 = k0 + 8;
            v[ks][0] = (k0 < 70) ? e0[k0 >> 1] : z2;
            v[ks][1] = (k0 < 70) ? e1[k0 >> 1] : z2;
            v[ks][2] = (k1 < 70) ? e0[k1 >> 1] : z2;
            v[ks][3] = (k1 < 70) ? e1[k1 >> 1] : z2;
        }
        #pragma unroll
        for (int ks = 0; ks < 5; ks++) {
            uint32_t ah[4], al[4];
            splitf2(v[ks][0], ah[0], al[0]);
            splitf2(v[ks][1], ah[1], al[1]);
            splitf2(v[ks][2], ah[2], al[2]);
            splitf2(v[ks][3], ah[3], al[3]);
            mma_n9<3>(Whi, Wlo, ks * 8 + qp, SWW, q, ah, al, C);
        }
    }

    // ---- epi1: H1 = relu(D1+b1) -> H^T hi/lo (per-mol region) ----
    {
        const int r0 = mloc + q, r1 = r0 + 8;
        #pragma unroll
        for (int n = 0; n < 9; n++) {
            const int d0 = n * 8 + qp * 2;
            float h00 = fmaxf(C[n][0] + smf[B1I + d0], 0.f);
            float h01 = fmaxf(C[n][1] + smf[B1I + d0 + 1], 0.f);
            float h10 = fmaxf(C[n][2] + smf[B1I + d0], 0.f);
            float h11 = fmaxf(C[n][3] + smf[B1I + d0 + 1], 0.f);
            uint16_t hh, hl;
            split2(h00, hh, hl); H16h[d0 * 72 + r0] = hh;       H16l[d0 * 72 + r0] = hl;
            split2(h01, hh, hl); H16h[(d0 + 1) * 72 + r0] = hh; H16l[(d0 + 1) * 72 + r0] = hl;
            split2(h10, hh, hl); H16h[d0 * 72 + r1] = hh;       H16l[d0 * 72 + r1] = hl;
            split2(h11, hh, hl); H16h[(d0 + 1) * 72 + r1] = hh; H16l[(d0 + 1) * 72 + r1] = hl;
        }
    }
    __syncthreads();   // H ready everywhere; W1 fully consumed

    {   // W2 split tiles over W1 (completes before the post-GEMM2 sync)
        const uint4* gw = (const uint4*)g_wt[1][0];
        uint4* sw = (uint4*)(sm + OFF_W);
        #pragma unroll
        for (int i = t; i < 2 * WTILE / 16; i += 256) sw[i] = gw[i];
    }

    // ================= GEMM2: D2 = A @ H1  (K=64, 2-term, A-hi only) ========
    #pragma unroll
    for (int n = 0; n < 9; n++)
        #pragma unroll
        for (int i = 0; i < 4; i++) C[n][i] = 0.f;
    #pragma unroll
    for (int ks = 0; ks < 4; ks++) {
        const int ra = (mloc + q) * SHW + ks * 8 + qp;
        uint32_t ah[4];
        ah[0] = Ahi[ra];     ah[1] = Ahi[ra + 8 * SHW];
        ah[2] = Ahi[ra + 4]; ah[3] = Ahi[ra + 8 * SHW + 4];
        mma_n9<2>(Hhi, Hlo, ks * 8 + qp, SHW, q, ah, ah, C);
    }
    __syncthreads();   // W2 stores complete

    // ================= GEMM3: D3 = D2 @ W2^T (A-frags chained in-register) ==
    float C3[9][4];
    #pragma unroll
    for (int n = 0; n < 9; n++)
        #pragma unroll
        for (int i = 0; i < 4; i++) C3[n][i] = 0.f;
    #pragma unroll
    for (int ks = 0; ks < 5; ks++) {
        uint32_t ah[4], al[4];
        splitf2(make_float2(C[2*ks][0], C[2*ks][1]), ah[0], al[0]);
        splitf2(make_float2(C[2*ks][2], C[2*ks][3]), ah[1], al[1]);
        if (ks < 4) {
            splitf2(make_float2(C[2*ks+1][0], C[2*ks+1][1]), ah[2], al[2]);
            splitf2(make_float2(C[2*ks+1][2], C[2*ks+1][3]), ah[3], al[3]);
        } else { ah[2] = al[2] = ah[3] = al[3] = 0u; }
        mma_n9<3>(Whi, Wlo, ks * 8 + qp, SWW, q, ah, al, C3);
    }

    // ---- epi3: pool partials y[d] += csum[r] * relu(D3[r][d]+b2[d]) ----
    {
        const float cs0 = smf[CSI + mrow + q];
        const float cs1 = smf[CSI + mrow + q + 8];
        #pragma unroll
        for (int n = 0; n < 9; n++) {
            #pragma unroll
            for (int j = 0; j < 2; j++) {
                const int d = n * 8 + qp * 2 + j;
                float v = cs0 * fmaxf(C3[n][j] + smf[B2I + d], 0.f)
                        + cs1 * fmaxf(C3[n][2 + j] + smf[B2I + d], 0.f);
                v += __shfl_xor_sync(0xFFFFFFFFu, v, 4);
                v += __shfl_xor_sync(0xFFFFFFFFu, v, 8);
                v += __shfl_xor_sync(0xFFFFFFFFu, v, 16);
                if (q == 0) smf[PLI + wid * 72 + d] = v;
            }
        }
    }
    __syncthreads();

    // reduce 4 warps per molecule
    if (t < 144) {
        const int mY = t / 72, d = t - mY * 72;
        float y = smf[PLI + (mY * 4 + 0) * 72 + d] + smf[PLI + (mY * 4 + 1) * 72 + d]
                + smf[PLI + (mY * 4 + 2) * 72 + d] + smf[PLI + (mY * 4 + 3) * 72 + d];
        smf[YI + t] = y;
    }
    __syncthreads();

    // head
    if (t < 22) {
        const int mH = t / 11, c = t - mH * 11;
        float s = smf[BPI + c];
        #pragma unroll 7
        for (int d = 0; d < 70; d++)
            s += smf[YI + mH * 72 + d] * __ldg(&wp[d * 11 + c]);
        const float* sv = sel + (size_t)(2 * bid + mH) * 7;
        #pragma unroll
        for (int e = 0; e < 7; e++)
            s += __ldg(&sv[e]) * __ldg(&wp[(70 + e) * 11 + c]);
        out[(size_t)(2 * bid + mH) * 11 + c] = s;
    }
}

extern "C" void kernel_launch(void* const* d_in, const int* in_sizes, int n_in,
                              void* d_out, int out_size)
{
    const int*   atoms = (const int*)  d_in[0];
    const float* adj   = (const float*)d_in[1];
    const float* sel   = (const float*)d_in[2];
    const float* emb   = (const float*)d_in[3];
    const float* w1    = (const float*)d_in[4];
    const float* b1    = (const float*)d_in[5];
    const float* w2    = (const float*)d_in[6];
    const float* b2    = (const float*)d_in[7];
    const float* wp    = (const float*)d_in[8];
    const float* bp    = (const float*)d_in[9];
    float* out = (float*)d_out;

    prep_w<<<(2 * 72 * 88 + 127) / 128, 128>>>(w1, w2);

    cudaFuncSetAttribute(pathway_mma4,
                         cudaFuncAttributeMaxDynamicSharedMemorySize, SMEM_BYTES);
    pathway_mma4<<<4096, 256, SMEM_BYTES>>>(atoms, adj, sel, emb,
                                            b1, b2, wp, bp, out);
}

// round 10
// speedup vs baseline: 1.2881x; 1.0212x over previous
#include <cuda_runtime.h>
#include <cuda_bf16.h>
#include <cstdint>

// ============================================================================
// PathwayPredictor, mma.sync bf16-split, 2 molecules/CTA, 128 threads,
// M=32 per warp (two m16 tiles share every B-fragment load).
// GEMM1: X(embed LDG frags) @ W1^T [K=80, 3-term]
// GEMM2: A(hi, smem frag tile built during load) @ H1 [K=64, 2-term]
// GEMM3: D2 (in-register chain) @ W2^T [K=80, 3-term]
// Adjacency load fused with fp32 colsum partials + bf16-hi fragment-tile build.
// pool collapse: y = colsum(A) @ relu(D3+b2); tiny head.
// ============================================================================

#define SWW 44   // W row stride, u32 words (88 bf16)
#define SHW 36   // H / A row stride, u32 words (72 bf16)

// smem float indices
#define B1I 0       // b1 padded [72]
#define B2I 72      // b2 padded [72]
#define BPI 144     // bp [16]
#define CSP 160     // colsum partials [4][128]
#define CSI 672     // colsum [128] (mol-major: mol*64 + col)
#define PLI 800     // pool partials [4][72]
#define YI  1088    // y [2][72]
// byte offsets
#define OFF_H 4992      // 2 x (72x72 hi + lo) b16 = 41472
#define OFF_W 46464     // 72x88 hi + lo = 25344 (W1 then W2)
#define OFF_A 71808     // 2 x (64x72 hi) = 18432
#define SMEM_BYTES 90240
#define WTILE 12672
#define HTILE 20736
#define ATILE_W 2304    // A tile size in u32 words

__device__ __align__(16) unsigned char g_wt[2][2][WTILE];  // [layer][hi/lo]

// ---------------- helpers ----------------
__device__ __forceinline__ void split2(float v, uint16_t& h, uint16_t& l) {
    __nv_bfloat16 bh = __float2bfloat16(v);
    h = *reinterpret_cast<uint16_t*>(&bh);
    __nv_bfloat16 bl = __float2bfloat16(v - __bfloat162float(bh));
    l = *reinterpret_cast<uint16_t*>(&bl);
}
__device__ __forceinline__ uint32_t packb(float2 v) {   // lo16=bf16(v.x), hi16=bf16(v.y)
    uint32_t r;
    asm("cvt.rn.satfinite.bf16x2.f32 %0, %1, %2;" : "=r"(r) : "f"(v.y), "f"(v.x));
    return r;
}
__device__ __forceinline__ void splitf2(float2 v, uint32_t& h, uint32_t& l) {
    h = packb(v);
    float hx = __uint_as_float(h << 16);
    float hy = __uint_as_float(h & 0xFFFF0000u);
    l = packb(make_float2(v.x - hx, v.y - hy));
}
__device__ __forceinline__ void mma16816(float c[4],
    const uint32_t a[4], uint32_t b0, uint32_t b1)
{
    asm volatile(
        "mma.sync.aligned.m16n8k16.row.col.f32.bf16.bf16.f32 "
        "{%0,%1,%2,%3},{%4,%5,%6,%7},{%8,%9},{%0,%1,%2,%3};"
        : "+f"(c[0]), "+f"(c[1]), "+f"(c[2]), "+f"(c[3])
        : "r"(a[0]), "r"(a[1]), "r"(a[2]), "r"(a[3]), "r"(b0), "r"(b1));
}

// 9 n-tiles, one k16 step, TWO m-tiles sharing each B-fragment load.
template<int TERMS>
__device__ __forceinline__ void mma_n9x2(
    const uint32_t* __restrict__ Bhi, const uint32_t* __restrict__ Blo,
    int rbase, int sb, int q,
    const uint32_t ah0[4], const uint32_t al0[4],
    const uint32_t ah1[4], const uint32_t al1[4],
    float C0[9][4], float C1[9][4])
{
    #pragma unroll
    for (int n = 0; n < 9; n++) {
        const int rb = (n * 8 + q) * sb + rbase;
        uint32_t bh0 = Bhi[rb], bh1 = Bhi[rb + 4];
        uint32_t bl0 = Blo[rb], bl1 = Blo[rb + 4];
        mma16816(C0[n], ah0, bh0, bh1);
        mma16816(C1[n], ah1, bh0, bh1);
        mma16816(C0[n], ah0, bl0, bl1);
        mma16816(C1[n], ah1, bl0, bl1);
        if (TERMS == 3) {
            mma16816(C0[n], al0, bh0, bh1);
            mma16816(C1[n], al1, bh0, bh1);
        }
    }
}

// ---------------- weight prep: W^T split tiles [72 n][88 k] hi/lo ----------------
__global__ void prep_w(const float* __restrict__ w1, const float* __restrict__ w2) {
    int idx = blockIdx.x * 128 + threadIdx.x;
    if (idx >= 2 * 72 * 88) return;
    int l = idx / (72 * 88);
    int r = idx % (72 * 88);
    int n = r / 88, k = r % 88;
    const float* w = l ? w2 : w1;
    float v = (n < 70 && k < 70) ? w[k * 70 + n] : 0.f;
    uint16_t h, lo; split2(v, h, lo);
    *(uint16_t*)(g_wt[l][0] + r * 2) = h;
    *(uint16_t*)(g_wt[l][1] + r * 2) = lo;
}

// ---------------- main kernel ----------------
__global__ __launch_bounds__(128, 2)
void pathway_mma5(const int* __restrict__ atoms, const float* __restrict__ adj,
                  const float* __restrict__ sel, const float* __restrict__ emb,
                  const float* __restrict__ b1, const float* __restrict__ b2,
                  const float* __restrict__ wp, const float* __restrict__ bp,
                  float* __restrict__ out)
{
    extern __shared__ __align__(16) unsigned char sm[];
    float* smf = (float*)sm;
    const int t = threadIdx.x, lane = t & 31, wid = t >> 5;
    const int bid = blockIdx.x;
    const int q = lane >> 2, qp = lane & 3;
    const int mol = wid >> 1;                 // molecule 0/1
    const int mrow = wid * 32;                // warp's global row base
    const int mloc = mrow & 63;               // 0 or 32 within molecule

    uint32_t* Whi = (uint32_t*)(sm + OFF_W);  uint32_t* Wlo = Whi + 72 * SWW;
    uint32_t* Hhi = (uint32_t*)(sm + OFF_H + mol * HTILE);
    uint32_t* Hlo = Hhi + 72 * SHW;
    uint16_t* H16h = (uint16_t*)(sm + OFF_H + mol * HTILE);
    uint16_t* H16l = H16h + 72 * 72;
    uint32_t* Ahi = (uint32_t*)(sm + OFF_A) + mol * ATILE_W;
    uint32_t* AhiAll = (uint32_t*)(sm + OFF_A);

    // ===== phase 0: adjacency load + fused colsum partials + A-hi tile =====
    {
        const float2* Ab = (const float2*)(adj + (size_t)bid * 8192);
        float2 cs0 = make_float2(0.f, 0.f), cs1 = make_float2(0.f, 0.f);
        const int c2 = t & 31;                // fixed f2-column per thread
        #pragma unroll
        for (int k = 0; k < 32; k++) {
            const int i = t + 128 * k;
            float2 v = __ldg(&Ab[i]);
            if (k < 16) { cs0.x += v.x; cs0.y += v.y; }
            else        { cs1.x += v.x; cs1.y += v.y; }
            const int gr = i >> 5;            // global row 0..127
            AhiAll[(gr >> 6) * ATILE_W + (gr & 63) * SHW + c2] = packb(v);
        }
        const int g = t >> 5, c0 = c2 * 2;
        smf[CSP + g * 128 + c0]          = cs0.x;
        smf[CSP + g * 128 + c0 + 1]      = cs0.y;
        smf[CSP + g * 128 + 64 + c0]     = cs1.x;
        smf[CSP + g * 128 + 64 + c0 + 1] = cs1.y;
    }
    {   // W1 split tiles
        const uint4* gw = (const uint4*)g_wt[0][0];
        uint4* sw = (uint4*)(sm + OFF_W);
        #pragma unroll
        for (int i = t; i < 2 * WTILE / 16; i += 128) sw[i] = gw[i];
    }
    if (t < 72) { smf[B1I + t] = (t < 70) ? b1[t] : 0.f;
                  smf[B2I + t] = (t < 70) ? b2[t] : 0.f; }
    if (t < 11) smf[BPI + t] = bp[t];
    __syncthreads();

    // colsum reduce (consumed in epi3, after >=1 more sync)
    smf[CSI + t] = smf[CSP + t] + smf[CSP + 128 + t]
                 + smf[CSP + 256 + t] + smf[CSP + 384 + t];

    float C0[9][4], C1[9][4];
    #pragma unroll
    for (int n = 0; n < 9; n++)
        #pragma unroll
        for (int i = 0; i < 4; i++) { C0[n][i] = 0.f; C1[n][i] = 0.f; }

    // ================= GEMM1: D1 = X @ W1^T (K=80, 3-term) =================
    {
        uint32_t xh[2][5][4], xl[2][5][4];
        const float2 z2 = make_float2(0.f, 0.f);
        #pragma unroll
        for (int m2 = 0; m2 < 2; m2++) {
            const int base = bid * 128 + mrow + m2 * 16 + q;
            const int a0i = __ldg(&atoms[base]);
            const int a1i = __ldg(&atoms[base + 8]);
            const float2* e0 = (const float2*)(emb + (size_t)a0i * 70);
            const float2* e1 = (const float2*)(emb + (size_t)a1i * 70);
            #pragma unroll
            for (int ks = 0; ks < 5; ks++) {
                const int k0 = 16 * ks + 2 * qp, k1 = k0 + 8;
                float2 v0 = (k0 < 70) ? e0[k0 >> 1] : z2;
                float2 v1 = (k0 < 70) ? e1[k0 >> 1] : z2;
                float2 v2 = (k1 < 70) ? e0[k1 >> 1] : z2;
                float2 v3 = (k1 < 70) ? e1[k1 >> 1] : z2;
                splitf2(v0, xh[m2][ks][0], xl[m2][ks][0]);
                splitf2(v1, xh[m2][ks][1], xl[m2][ks][1]);
                splitf2(v2, xh[m2][ks][2], xl[m2][ks][2]);
                splitf2(v3, xh[m2][ks][3], xl[m2][ks][3]);
            }
        }
        #pragma unroll
        for (int ks = 0; ks < 5; ks++)
            mma_n9x2<3>(Whi, Wlo, ks * 8 + qp, SWW, q,
                        xh[0][ks], xl[0][ks], xh[1][ks], xl[1][ks], C0, C1);
    }

    // ---- epi1: H1 = relu(D1+b1) -> H^T hi/lo ----
    #pragma unroll
    for (int m2 = 0; m2 < 2; m2++) {
        float (*C)[4] = m2 ? C1 : C0;
        const int r0 = mloc + m2 * 16 + q, r1 = r0 + 8;
        #pragma unroll
        for (int n = 0; n < 9; n++) {
            const int d0 = n * 8 + qp * 2;
            float h00 = fmaxf(C[n][0] + smf[B1I + d0], 0.f);
            float h01 = fmaxf(C[n][1] + smf[B1I + d0 + 1], 0.f);
            float h10 = fmaxf(C[n][2] + smf[B1I + d0], 0.f);
            float h11 = fmaxf(C[n][3] + smf[B1I + d0 + 1], 0.f);
            uint16_t hh, hl;
            split2(h00, hh, hl); H16h[d0 * 72 + r0] = hh;       H16l[d0 * 72 + r0] = hl;
            split2(h01, hh, hl); H16h[(d0 + 1) * 72 + r0] = hh; H16l[(d0 + 1) * 72 + r0] = hl;
            split2(h10, hh, hl); H16h[d0 * 72 + r1] = hh;       H16l[d0 * 72 + r1] = hl;
            split2(h11, hh, hl); H16h[(d0 + 1) * 72 + r1] = hh; H16l[(d0 + 1) * 72 + r1] = hl;
        }
    }
    __syncthreads();   // H ready; W1 consumed

    {   // W2 split tiles over W1 (completes before post-GEMM2 sync)
        const uint4* gw = (const uint4*)g_wt[1][0];
        uint4* sw = (uint4*)(sm + OFF_W);
        #pragma unroll
        for (int i = t; i < 2 * WTILE / 16; i += 128) sw[i] = gw[i];
    }

    // ================= GEMM2: D2 = A @ H1 (K=64, 2-term) =================
    #pragma unroll
    for (int n = 0; n < 9; n++)
        #pragma unroll
        for (int i = 0; i < 4; i++) { C0[n][i] = 0.f; C1[n][i] = 0.f; }
    #pragma unroll
    for (int ks = 0; ks < 4; ks++) {
        const int ra = (mloc + q) * SHW + ks * 8 + qp;
        uint32_t a0[4], a1[4];
        a0[0] = Ahi[ra];               a0[1] = Ahi[ra + 8 * SHW];
        a0[2] = Ahi[ra + 4];           a0[3] = Ahi[ra + 8 * SHW + 4];
        a1[0] = Ahi[ra + 16 * SHW];    a1[1] = Ahi[ra + 24 * SHW];
        a1[2] = Ahi[ra + 16 * SHW + 4];a1[3] = Ahi[ra + 24 * SHW + 4];
        mma_n9x2<2>(Hhi, Hlo, ks * 8 + qp, SHW, q, a0, a0, a1, a1, C0, C1);
    }
    __syncthreads();   // W2 stores complete

    // ================= GEMM3: D3 = D2 @ W2^T (chained, K=80, 3-term) =======
    float C3a[9][4], C3b[9][4];
    #pragma unroll
    for (int n = 0; n < 9; n++)
        #pragma unroll
        for (int i = 0; i < 4; i++) { C3a[n][i] = 0.f; C3b[n][i] = 0.f; }
    #pragma unroll
    for (int ks = 0; ks < 5; ks++) {
        uint32_t ah0[4], al0[4], ah1[4], al1[4];
        splitf2(make_float2(C0[2*ks][0], C0[2*ks][1]), ah0[0], al0[0]);
        splitf2(make_float2(C0[2*ks][2], C0[2*ks][3]), ah0[1], al0[1]);
        splitf2(make_float2(C1[2*ks][0], C1[2*ks][1]), ah1[0], al1[0]);
        splitf2(make_float2(C1[2*ks][2], C1[2*ks][3]), ah1[1], al1[1]);
        if (ks < 4) {
            splitf2(make_float2(C0[2*ks+1][0], C0[2*ks+1][1]), ah0[2], al0[2]);
            splitf2(make_float2(C0[2*ks+1][2], C0[2*ks+1][3]), ah0[3], al0[3]);
            splitf2(make_float2(C1[2*ks+1][0], C1[2*ks+1][1]), ah1[2], al1[2]);
            splitf2(make_float2(C1[2*ks+1][2], C1[2*ks+1][3]), ah1[3], al1[3]);
        } else {
            ah0[2] = al0[2] = ah0[3] = al0[3] = 0u;
            ah1[2] = al1[2] = ah1[3] = al1[3] = 0u;
        }
        mma_n9x2<3>(Whi, Wlo, ks * 8 + qp, SWW, q,
                    ah0, al0, ah1, al1, C3a, C3b);
    }

    // ---- epi3: pool partials y[d] += csum[r] * relu(D3[r][d]+b2[d]) ----
    {
        const float cs00 = smf[CSI + mrow + q];
        const float cs01 = smf[CSI + mrow + q + 8];
        const float cs10 = smf[CSI + mrow + q + 16];
        const float cs11 = smf[CSI + mrow + q + 24];
        #pragma unroll
        for (int n = 0; n < 9; n++) {
            #pragma unroll
            for (int j = 0; j < 2; j++) {
                const int d = n * 8 + qp * 2 + j;
                const float bb = smf[B2I + d];
                float v = cs00 * fmaxf(C3a[n][j] + bb, 0.f)
                        + cs01 * fmaxf(C3a[n][2 + j] + bb, 0.f)
                        + cs10 * fmaxf(C3b[n][j] + bb, 0.f)
                        + cs11 * fmaxf(C3b[n][2 + j] + bb, 0.f);
                v += __shfl_xor_sync(0xFFFFFFFFu, v, 4);
                v += __shfl_xor_sync(0xFFFFFFFFu, v, 8);
                v += __shfl_xor_sync(0xFFFFFFFFu, v, 16);
                if (q == 0) smf[PLI + wid * 72 + d] = v;
            }
        }
    }
    __syncthreads();

    // reduce 2 warps per molecule (144 entries, 128 threads -> strided)
    for (int i = t; i < 144; i += 128) {
        const int mY = i / 72, d = i - mY * 72;
        smf[YI + i] = smf[PLI + (mY * 2 + 0) * 72 + d]
                    + smf[PLI + (mY * 2 + 1) * 72 + d];
    }
    __syncthreads();

    // head
    if (t < 22) {
        const int mH = t / 11, c = t - mH * 11;
        float s = smf[BPI + c];
        #pragma unroll 7
        for (int d = 0; d < 70; d++)
            s += smf[YI + mH * 72 + d] * __ldg(&wp[d * 11 + c]);
        const float* sv = sel + (size_t)(2 * bid + mH) * 7;
        #pragma unroll
        for (int e = 0; e < 7; e++)
            s += __ldg(&sv[e]) * __ldg(&wp[(70 + e) * 11 + c]);
        out[(size_t)(2 * bid + mH) * 11 + c] = s;
    }
}

extern "C" void kernel_launch(void* const* d_in, const int* in_sizes, int n_in,
                              void* d_out, int out_size)
{
    const int*   atoms = (const int*)  d_in[0];
    const float* adj   = (const float*)d_in[1];
    const float* sel   = (const float*)d_in[2];
    const float* emb   = (const float*)d_in[3];
    const float* w1    = (const float*)d_in[4];
    const float* b1    = (const float*)d_in[5];
    const float* w2    = (const float*)d_in[6];
    const float* b2    = (const float*)d_in[7];
    const float* wp    = (const float*)d_in[8];
    const float* bp    = (const float*)d_in[9];
    float* out = (float*)d_out;

    prep_w<<<(2 * 72 * 88 + 127) / 128, 128>>>(w1, w2);

    cudaFuncSetAttribute(pathway_mma5,
                         cudaFuncAttributeMaxDynamicSharedMemorySize, SMEM_BYTES);
    pathway_mma5<<<4096, 128, SMEM_BYTES>>>(atoms, adj, sel, emb,
                                            b1, b2, wp, bp, out);
}

// round 12
// speedup vs baseline: 1.3604x; 1.0561x over previous
#include <cuda_runtime.h>
#include <cuda_bf16.h>
#include <cstdint>

// ============================================================================
// PathwayPredictor, mma.sync bf16-split, 2 molecules/CTA, 128 threads,
// M=32 per warp, 3 CTAs/SM (smem 70.0KB, regs capped via launch_bounds).
// GEMM1: X(embed LDG frags, double-buffered) @ W1^T [K=80, 3-term]
// GEMM2: A(JIT gmem frags, L2-warm, double-buffered) @ H1(smem) [K=64, 2-term]
// GEMM3: D2 (in-register chain) @ W2^T [K=80, 3-term]
// pool collapse: y = colsum(A) @ relu(D3+b2); tiny head.
// ============================================================================

#define SWW 44   // W row stride, u32 words (88 bf16)
#define SHW 36   // H row stride, u32 words (72 bf16)

// smem float indices (CSP overlaid by PLI/YI after colsum reduce; CSI disjoint)
#define B1I 0       // b1 padded [72]
#define B2I 72      // b2 padded [72]
#define BPI 144     // bp [16]
#define CSP 160     // colsum partials [4][128] (160..671; dead after reduce)
#define PLI 160     // pool partials [4][72]  (overlays CSP, used post-epi3)
#define YI  448     // y [2][72]              (overlays CSP, used post-epi3)
#define CSI 672     // colsum [128] (672..799, DISJOINT from CSP)
// byte offsets
#define OFF_H 3200      // 2 x (72x72 hi + lo) b16 = 41472
#define OFF_W 44672     // 72x88 hi + lo = 25344 (W1 then W2)
#define SMEM_BYTES 70016
#define WTILE 12672
#define HTILE 20736

__device__ __align__(16) unsigned char g_wt[2][2][WTILE];  // [layer][hi/lo]

// ---------------- helpers ----------------
__device__ __forceinline__ void split2(float v, uint16_t& h, uint16_t& l) {
    __nv_bfloat16 bh = __float2bfloat16(v);
    h = *reinterpret_cast<uint16_t*>(&bh);
    __nv_bfloat16 bl = __float2bfloat16(v - __bfloat162float(bh));
    l = *reinterpret_cast<uint16_t*>(&bl);
}
__device__ __forceinline__ uint32_t packb(float2 v) {   // lo16=bf16(v.x), hi16=bf16(v.y)
    uint32_t r;
    asm("cvt.rn.satfinite.bf16x2.f32 %0, %1, %2;" : "=r"(r) : "f"(v.y), "f"(v.x));
    return r;
}
__device__ __forceinline__ void splitf2(float2 v, uint32_t& h, uint32_t& l) {
    h = packb(v);
    float hx = __uint_as_float(h << 16);
    float hy = __uint_as_float(h & 0xFFFF0000u);
    l = packb(make_float2(v.x - hx, v.y - hy));
}
__device__ __forceinline__ void mma16816(float c[4],
    const uint32_t a[4], uint32_t b0, uint32_t b1)
{
    asm volatile(
        "mma.sync.aligned.m16n8k16.row.col.f32.bf16.bf16.f32 "
        "{%0,%1,%2,%3},{%4,%5,%6,%7},{%8,%9},{%0,%1,%2,%3};"
        : "+f"(c[0]), "+f"(c[1]), "+f"(c[2]), "+f"(c[3])
        : "r"(a[0]), "r"(a[1]), "r"(a[2]), "r"(a[3]), "r"(b0), "r"(b1));
}

// 9 n-tiles, one k16 step, TWO m-tiles sharing each B-fragment load.
template<int TERMS>
__device__ __forceinline__ void mma_n9x2(
    const uint32_t* __restrict__ Bhi, const uint32_t* __restrict__ Blo,
    int rbase, int sb, int q,
    const uint32_t ah0[4], const uint32_t al0[4],
    const uint32_t ah1[4], const uint32_t al1[4],
    float C0[9][4], float C1[9][4])
{
    #pragma unroll
    for (int n = 0; n < 9; n++) {
        const int rb = (n * 8 + q) * sb + rbase;
        uint32_t bh0 = Bhi[rb], bh1 = Bhi[rb + 4];
        uint32_t bl0 = Blo[rb], bl1 = Blo[rb + 4];
        mma16816(C0[n], ah0, bh0, bh1);
        mma16816(C1[n], ah1, bh0, bh1);
        mma16816(C0[n], ah0, bl0, bl1);
        mma16816(C1[n], ah1, bl0, bl1);
        if (TERMS == 3) {
            mma16816(C0[n], al0, bh0, bh1);
            mma16816(C1[n], al1, bh0, bh1);
        }
    }
}

// ---------------- weight prep: W^T split tiles [72 n][88 k] hi/lo ----------------
__global__ void prep_w(const float* __restrict__ w1, const float* __restrict__ w2) {
    int idx = blockIdx.x * 128 + threadIdx.x;
    if (idx >= 2 * 72 * 88) return;
    int l = idx / (72 * 88);
    int r = idx % (72 * 88);
    int n = r / 88, k = r % 88;
    const float* w = l ? w2 : w1;
    float v = (n < 70 && k < 70) ? w[k * 70 + n] : 0.f;
    uint16_t h, lo; split2(v, h, lo);
    *(uint16_t*)(g_wt[l][0] + r * 2) = h;
    *(uint16_t*)(g_wt[l][1] + r * 2) = lo;
}

// ---------------- main kernel ----------------
__global__ __launch_bounds__(128, 3)
void pathway_mma6(const int* __restrict__ atoms, const float* __restrict__ adj,
                  const float* __restrict__ sel, const float* __restrict__ emb,
                  const float* __restrict__ b1, const float* __restrict__ b2,
                  const float* __restrict__ wp, const float* __restrict__ bp,
                  float* __restrict__ out)
{
    extern __shared__ __align__(16) unsigned char sm[];
    float* smf = (float*)sm;
    const int t = threadIdx.x, lane = t & 31, wid = t >> 5;
    const int bid = blockIdx.x;
    const int q = lane >> 2, qp = lane & 3;
    const int mol = wid >> 1;                 // molecule 0/1
    const int mrow = wid * 32;                // warp's global row base
    const int mloc = mrow & 63;               // 0 or 32 within molecule

    uint32_t* Whi = (uint32_t*)(sm + OFF_W);  uint32_t* Wlo = Whi + 72 * SWW;
    uint32_t* Hhi = (uint32_t*)(sm + OFF_H + mol * HTILE);
    uint32_t* Hlo = Hhi + 72 * SHW;
    uint16_t* H16h = (uint16_t*)(sm + OFF_H + mol * HTILE);
    uint16_t* H16l = H16h + 72 * 72;

    // ===== phase 0: colsum partials (streams adjacency through L2) =====
    {
        const float2* Ab = (const float2*)(adj + (size_t)bid * 8192);
        float2 cs0 = make_float2(0.f, 0.f), cs1 = make_float2(0.f, 0.f);
        #pragma unroll
        for (int k = 0; k < 32; k++) {
            float2 v = __ldg(&Ab[t + 128 * k]);
            if (k < 16) { cs0.x += v.x; cs0.y += v.y; }
            else        { cs1.x += v.x; cs1.y += v.y; }
        }
        const int g = t >> 5, c0 = (t & 31) * 2;
        smf[CSP + g * 128 + c0]          = cs0.x;
        smf[CSP + g * 128 + c0 + 1]      = cs0.y;
        smf[CSP + g * 128 + 64 + c0]     = cs1.x;
        smf[CSP + g * 128 + 64 + c0 + 1] = cs1.y;
    }
    {   // W1 split tiles
        const uint4* gw = (const uint4*)g_wt[0][0];
        uint4* sw = (uint4*)(sm + OFF_W);
        #pragma unroll
        for (int i = t; i < 2 * WTILE / 16; i += 128) sw[i] = gw[i];
    }
    if (t < 72) { smf[B1I + t] = (t < 70) ? b1[t] : 0.f;
                  smf[B2I + t] = (t < 70) ? b2[t] : 0.f; }
    if (t < 11) smf[BPI + t] = bp[t];
    __syncthreads();

    // colsum reduce -> CSI (disjoint from CSP; CSP dead after this)
    smf[CSI + t] = smf[CSP + t] + smf[CSP + 128 + t]
                 + smf[CSP + 256 + t] + smf[CSP + 384 + t];

    float C0[9][4], C1[9][4];
    #pragma unroll
    for (int n = 0; n < 9; n++)
        #pragma unroll
        for (int i = 0; i < 4; i++) { C0[n][i] = 0.f; C1[n][i] = 0.f; }

    // ================= GEMM1: D1 = X @ W1^T (K=80, 3-term, dbl-buffered) ===
    {
        const int abase = bid * 128 + mrow + q;
        const float2* e00 = (const float2*)(emb + (size_t)__ldg(&atoms[abase])      * 70);
        const float2* e01 = (const float2*)(emb + (size_t)__ldg(&atoms[abase + 8])  * 70);
        const float2* e10 = (const float2*)(emb + (size_t)__ldg(&atoms[abase + 16]) * 70);
        const float2* e11 = (const float2*)(emb + (size_t)__ldg(&atoms[abase + 24]) * 70);
        const float2 z2 = make_float2(0.f, 0.f);

        float2 va[8], vb[8];
        {
            const int k0 = 2 * qp, k1 = k0 + 8;
            va[0] = __ldg(&e00[k0 >> 1]); va[1] = __ldg(&e01[k0 >> 1]);
            va[2] = __ldg(&e00[k1 >> 1]); va[3] = __ldg(&e01[k1 >> 1]);
            va[4] = __ldg(&e10[k0 >> 1]); va[5] = __ldg(&e11[k0 >> 1]);
            va[6] = __ldg(&e10[k1 >> 1]); va[7] = __ldg(&e11[k1 >> 1]);
        }
        #pragma unroll
        for (int ks = 0; ks < 5; ks++) {
            float2* cur = (ks & 1) ? vb : va;
            float2* nxt = (ks & 1) ? va : vb;
            if (ks < 4) {
                const int k0 = 16 * (ks + 1) + 2 * qp, k1 = k0 + 8;
                nxt[0] = (k0 < 70) ? __ldg(&e00[k0 >> 1]) : z2;
                nxt[1] = (k0 < 70) ? __ldg(&e01[k0 >> 1]) : z2;
                nxt[2] = (k1 < 70) ? __ldg(&e00[k1 >> 1]) : z2;
                nxt[3] = (k1 < 70) ? __ldg(&e01[k1 >> 1]) : z2;
                nxt[4] = (k0 < 70) ? __ldg(&e10[k0 >> 1]) : z2;
                nxt[5] = (k0 < 70) ? __ldg(&e11[k0 >> 1]) : z2;
                nxt[6] = (k1 < 70) ? __ldg(&e10[k1 >> 1]) : z2;
                nxt[7] = (k1 < 70) ? __ldg(&e11[k1 >> 1]) : z2;
            }
            uint32_t ah0[4], al0[4], ah1[4], al1[4];
            splitf2(cur[0], ah0[0], al0[0]);
            splitf2(cur[1], ah0[1], al0[1]);
            splitf2(cur[2], ah0[2], al0[2]);
            splitf2(cur[3], ah0[3], al0[3]);
            splitf2(cur[4], ah1[0], al1[0]);
            splitf2(cur[5], ah1[1], al1[1]);
            splitf2(cur[6], ah1[2], al1[2]);
            splitf2(cur[7], ah1[3], al1[3]);
            mma_n9x2<3>(Whi, Wlo, ks * 8 + qp, SWW, q,
                        ah0, al0, ah1, al1, C0, C1);
        }
    }

    // ---- epi1: H1 = relu(D1+b1) -> H^T hi/lo ----
    #pragma unroll
    for (int m2 = 0; m2 < 2; m2++) {
        float (*C)[4] = m2 ? C1 : C0;
        const int r0 = mloc + m2 * 16 + q, r1 = r0 + 8;
        #pragma unroll
        for (int n = 0; n < 9; n++) {
            const int d0 = n * 8 + qp * 2;
            float h00 = fmaxf(C[n][0] + smf[B1I + d0], 0.f);
            float h01 = fmaxf(C[n][1] + smf[B1I + d0 + 1], 0.f);
            float h10 = fmaxf(C[n][2] + smf[B1I + d0], 0.f);
            float h11 = fmaxf(C[n][3] + smf[B1I + d0 + 1], 0.f);
            uint16_t hh, hl;
            split2(h00, hh, hl); H16h[d0 * 72 + r0] = hh;       H16l[d0 * 72 + r0] = hl;
            split2(h01, hh, hl); H16h[(d0 + 1) * 72 + r0] = hh; H16l[(d0 + 1) * 72 + r0] = hl;
            split2(h10, hh, hl); H16h[d0 * 72 + r1] = hh;       H16l[d0 * 72 + r1] = hl;
            split2(h11, hh, hl); H16h[(d0 + 1) * 72 + r1] = hh; H16l[(d0 + 1) * 72 + r1] = hl;
        }
    }
    __syncthreads();   // H ready; W1 consumed

    {   // W2 split tiles over W1 (completes before post-GEMM2 sync)
        const uint4* gw = (const uint4*)g_wt[1][0];
        uint4* sw = (uint4*)(sm + OFF_W);
        #pragma unroll
        for (int i = t; i < 2 * WTILE / 16; i += 128) sw[i] = gw[i];
    }

    // ============ GEMM2: D2 = A @ H1 (K=64, 2-term, JIT A-frags) ===========
    #pragma unroll
    for (int n = 0; n < 9; n++)
        #pragma unroll
        for (int i = 0; i < 4; i++) { C0[n][i] = 0.f; C1[n][i] = 0.f; }
    {
        const float2* A2 = (const float2*)(adj + ((size_t)(2 * bid) + mol) * 4096);
        const int rb = (mloc + q) * 32;
        float2 va[8], vb[8];
        {
            const int cp0 = qp, cp1 = qp + 4;
            va[0] = __ldg(&A2[rb + cp0]);       va[1] = __ldg(&A2[rb + 256 + cp0]);
            va[2] = __ldg(&A2[rb + cp1]);       va[3] = __ldg(&A2[rb + 256 + cp1]);
            va[4] = __ldg(&A2[rb + 512 + cp0]); va[5] = __ldg(&A2[rb + 768 + cp0]);
            va[6] = __ldg(&A2[rb + 512 + cp1]); va[7] = __ldg(&A2[rb + 768 + cp1]);
        }
        #pragma unroll
        for (int ks = 0; ks < 4; ks++) {
            float2* cur = (ks & 1) ? vb : va;
            float2* nxt = (ks & 1) ? va : vb;
            if (ks < 3) {
                const int cp0 = 8 * (ks + 1) + qp, cp1 = cp0 + 4;
                nxt[0] = __ldg(&A2[rb + cp0]);       nxt[1] = __ldg(&A2[rb + 256 + cp0]);
                nxt[2] = __ldg(&A2[rb + cp1]);       nxt[3] = __ldg(&A2[rb + 256 + cp1]);
                nxt[4] = __ldg(&A2[rb + 512 + cp0]); nxt[5] = __ldg(&A2[rb + 768 + cp0]);
                nxt[6] = __ldg(&A2[rb + 512 + cp1]); nxt[7] = __ldg(&A2[rb + 768 + cp1]);
            }
            uint32_t a0[4], a1[4];
            a0[0] = packb(cur[0]); a0[1] = packb(cur[1]);
            a0[2] = packb(cur[2]); a0[3] = packb(cur[3]);
            a1[0] = packb(cur[4]); a1[1] = packb(cur[5]);
            a1[2] = packb(cur[6]); a1[3] = packb(cur[7]);
            mma_n9x2<2>(Hhi, Hlo, ks * 8 + qp, SHW, q, a0, a0, a1, a1, C0, C1);
        }
    }
    __syncthreads();   // W2 stores complete

    // ================= GEMM3: D3 = D2 @ W2^T (chained, K=80, 3-term) =======
    float C3a[9][4], C3b[9][4];
    #pragma unroll
    for (int n = 0; n < 9; n++)
        #pragma unroll
        for (int i = 0; i < 4; i++) { C3a[n][i] = 0.f; C3b[n][i] = 0.f; }
    #pragma unroll
    for (int ks = 0; ks < 5; ks++) {
        uint32_t ah0[4], al0[4], ah1[4], al1[4];
        splitf2(make_float2(C0[2*ks][0], C0[2*ks][1]), ah0[0], al0[0]);
        splitf2(make_float2(C0[2*ks][2], C0[2*ks][3]), ah0[1], al0[1]);
        splitf2(make_float2(C1[2*ks][0], C1[2*ks][1]), ah1[0], al1[0]);
        splitf2(make_float2(C1[2*ks][2], C1[2*ks][3]), ah1[1], al1[1]);
        if (ks < 4) {
            splitf2(make_float2(C0[2*ks+1][0], C0[2*ks+1][1]), ah0[2], al0[2]);
            splitf2(make_float2(C0[2*ks+1][2], C0[2*ks+1][3]), ah0[3], al0[3]);
            splitf2(make_float2(C1[2*ks+1][0], C1[2*ks+1][1]), ah1[2], al1[2]);
            splitf2(make_float2(C1[2*ks+1][2], C1[2*ks+1][3]), ah1[3], al1[3]);
        } else {
            ah0[2] = al0[2] = ah0[3] = al0[3] = 0u;
            ah1[2] = al1[2] = ah1[3] = al1[3] = 0u;
        }
        mma_n9x2<3>(Whi, Wlo, ks * 8 + qp, SWW, q,
                    ah0, al0, ah1, al1, C3a, C3b);
    }

    // ---- epi3: pool partials y[d] += csum[r] * relu(D3[r][d]+b2[d]) ----
    {
        const float cs00 = smf[CSI + mrow + q];
        const float cs01 = smf[CSI + mrow + q + 8];
        const float cs10 = smf[CSI + mrow + q + 16];
        const float cs11 = smf[CSI + mrow + q + 24];
        #pragma unroll
        for (int n = 0; n < 9; n++) {
            #pragma unroll
            for (int j = 0; j < 2; j++) {
                const int d = n * 8 + qp * 2 + j;
                const float bb = smf[B2I + d];
                float v = cs00 * fmaxf(C3a[n][j] + bb, 0.f)
                        + cs01 * fmaxf(C3a[n][2 + j] + bb, 0.f)
                        + cs10 * fmaxf(C3b[n][j] + bb, 0.f)
                        + cs11 * fmaxf(C3b[n][2 + j] + bb, 0.f);
                v += __shfl_xor_sync(0xFFFFFFFFu, v, 4);
                v += __shfl_xor_sync(0xFFFFFFFFu, v, 8);
                v += __shfl_xor_sync(0xFFFFFFFFu, v, 16);
                if (q == 0) smf[PLI + wid * 72 + d] = v;
            }
        }
    }
    __syncthreads();

    // reduce 2 warps per molecule (144 entries, strided over 128 threads)
    for (int i = t; i < 144; i += 128) {
        const int mY = i / 72, d = i - mY * 72;
        smf[YI + i] = smf[PLI + (mY * 2 + 0) * 72 + d]
                    + smf[PLI + (mY * 2 + 1) * 72 + d];
    }
    __syncthreads();

    // head
    if (t < 22) {
        const int mH = t / 11, c = t - mH * 11;
        float s = smf[BPI + c];
        #pragma unroll 7
        for (int d = 0; d < 70; d++)
            s += smf[YI + mH * 72 + d] * __ldg(&wp[d * 11 + c]);
        const float* sv = sel + (size_t)(2 * bid + mH) * 7;
        #pragma unroll
        for (int e = 0; e < 7; e++)
            s += __ldg(&sv[e]) * __ldg(&wp[(70 + e) * 11 + c]);
        out[(size_t)(2 * bid + mH) * 11 + c] = s;
    }
}

extern "C" void kernel_launch(void* const* d_in, const int* in_sizes, int n_in,
                              void* d_out, int out_size)
{
    const int*   atoms = (const int*)  d_in[0];
    const float* adj   = (const float*)d_in[1];
    const float* sel   = (const float*)d_in[2];
    const float* emb   = (const float*)d_in[3];
    const float* w1    = (const float*)d_in[4];
    const float* b1    = (const float*)d_in[5];
    const float* w2    = (const float*)d_in[6];
    const float* b2    = (const float*)d_in[7];
    const float* wp    = (const float*)d_in[8];
    const float* bp    = (const float*)d_in[9];
    float* out = (float*)d_out;

    prep_w<<<(2 * 72 * 88 + 127) / 128, 128>>>(w1, w2);

    cudaFuncSetAttribute(pathway_mma6,
                         cudaFuncAttributeMaxDynamicSharedMemorySize, SMEM_BYTES);
    pathway_mma6<<<4096, 128, SMEM_BYTES>>>(atoms, adj, sel, emb,
                                            b1, b2, wp, bp, out);
}

// round 13
// speedup vs baseline: 1.6315x; 1.1992x over previous
#include <cuda_runtime.h>
#include <cuda_bf16.h>
#include <cstdint>

// ============================================================================
// PathwayPredictor, mma.sync bf16-split, 2 molecules/CTA, 128 threads,
// M=32 per warp, 3 CTAs/SM (smem 49.3KB, regs capped via launch_bounds).
// GEMM1: X(embed LDG frags, double-buffered) @ W1^T [K=80, 3-term]
// GEMM2: A(JIT gmem frags) @ H1(smem, hi only)      [K=64, 1-term bf16]
//        (valid: A>=0, H>=0 -> positive-sum GEMM, rounding errors cancel)
// GEMM3: D2 (in-register chain) @ W2^T              [K=80, 3-term]
// pool collapse: y = colsum(A) @ relu(D3+b2); tiny head.
// ============================================================================

#define SWW 44   // W row stride, u32 words (88 bf16)
#define SHW 36   // H row stride, u32 words (72 bf16)

// smem float indices (CSP overlaid by PLI/YI after colsum reduce; CSI disjoint)
#define B1I 0       // b1 padded [72]
#define B2I 72      // b2 padded [72]
#define BPI 144     // bp [16]
#define CSP 160     // colsum partials [4][128] (160..671; dead after reduce)
#define PLI 160     // pool partials [4][72]  (overlays CSP, used post-epi3)
#define YI  448     // y [2][72]              (overlays CSP, used post-epi3)
#define CSI 672     // colsum [128] (672..799, DISJOINT from CSP)
// byte offsets
#define OFF_H 3200      // 2 x (72x72 hi) b16 = 20736
#define OFF_W 23936     // 72x88 hi + lo = 25344 (W1 then W2)
#define SMEM_BYTES 49280
#define WTILE 12672
#define HTILE 10368     // per-mol H tile (hi only)

__device__ __align__(16) unsigned char g_wt[2][2][WTILE];  // [layer][hi/lo]

// ---------------- helpers ----------------
__device__ __forceinline__ uint16_t bf16h(float v) {
    __nv_bfloat16 b = __float2bfloat16(v);
    return *reinterpret_cast<uint16_t*>(&b);
}
__device__ __forceinline__ void split2(float v, uint16_t& h, uint16_t& l) {
    __nv_bfloat16 bh = __float2bfloat16(v);
    h = *reinterpret_cast<uint16_t*>(&bh);
    __nv_bfloat16 bl = __float2bfloat16(v - __bfloat162float(bh));
    l = *reinterpret_cast<uint16_t*>(&bl);
}
__device__ __forceinline__ uint32_t packb(float2 v) {   // lo16=bf16(v.x), hi16=bf16(v.y)
    uint32_t r;
    asm("cvt.rn.satfinite.bf16x2.f32 %0, %1, %2;" : "=r"(r) : "f"(v.y), "f"(v.x));
    return r;
}
__device__ __forceinline__ void splitf2(float2 v, uint32_t& h, uint32_t& l) {
    h = packb(v);
    float hx = __uint_as_float(h << 16);
    float hy = __uint_as_float(h & 0xFFFF0000u);
    l = packb(make_float2(v.x - hx, v.y - hy));
}
__device__ __forceinline__ void mma16816(float c[4],
    const uint32_t a[4], uint32_t b0, uint32_t b1)
{
    asm volatile(
        "mma.sync.aligned.m16n8k16.row.col.f32.bf16.bf16.f32 "
        "{%0,%1,%2,%3},{%4,%5,%6,%7},{%8,%9},{%0,%1,%2,%3};"
        : "+f"(c[0]), "+f"(c[1]), "+f"(c[2]), "+f"(c[3])
        : "r"(a[0]), "r"(a[1]), "r"(a[2]), "r"(a[3]), "r"(b0), "r"(b1));
}

// 9 n-tiles, one k16 step, TWO m-tiles sharing each B-fragment load.
// TERMS=1: Ahi*Bhi only. TERMS>=2: +Ahi*Blo. TERMS==3: +Alo*Bhi.
template<int TERMS>
__device__ __forceinline__ void mma_n9x2(
    const uint32_t* __restrict__ Bhi, const uint32_t* __restrict__ Blo,
    int rbase, int sb, int q,
    const uint32_t ah0[4], const uint32_t al0[4],
    const uint32_t ah1[4], const uint32_t al1[4],
    float C0[9][4], float C1[9][4])
{
    #pragma unroll
    for (int n = 0; n < 9; n++) {
        const int rb = (n * 8 + q) * sb + rbase;
        uint32_t bh0 = Bhi[rb], bh1 = Bhi[rb + 4];
        mma16816(C0[n], ah0, bh0, bh1);
        mma16816(C1[n], ah1, bh0, bh1);
        if (TERMS >= 2) {
            uint32_t bl0 = Blo[rb], bl1 = Blo[rb + 4];
            mma16816(C0[n], ah0, bl0, bl1);
            mma16816(C1[n], ah1, bl0, bl1);
        }
        if (TERMS == 3) {
            mma16816(C0[n], al0, bh0, bh1);
            mma16816(C1[n], al1, bh0, bh1);
        }
    }
}

// ---------------- weight prep: W^T split tiles [72 n][88 k] hi/lo ----------------
__global__ void prep_w(const float* __restrict__ w1, const float* __restrict__ w2) {
    int idx = blockIdx.x * 128 + threadIdx.x;
    if (idx >= 2 * 72 * 88) return;
    int l = idx / (72 * 88);
    int r = idx % (72 * 88);
    int n = r / 88, k = r % 88;
    const float* w = l ? w2 : w1;
    float v = (n < 70 && k < 70) ? w[k * 70 + n] : 0.f;
    uint16_t h, lo; split2(v, h, lo);
    *(uint16_t*)(g_wt[l][0] + r * 2) = h;
    *(uint16_t*)(g_wt[l][1] + r * 2) = lo;
}

// ---------------- main kernel ----------------
__global__ __launch_bounds__(128, 3)
void pathway_mma7(const int* __restrict__ atoms, const float* __restrict__ adj,
                  const float* __restrict__ sel, const float* __restrict__ emb,
                  const float* __restrict__ b1, const float* __restrict__ b2,
                  const float* __restrict__ wp, const float* __restrict__ bp,
                  float* __restrict__ out)
{
    extern __shared__ __align__(16) unsigned char sm[];
    float* smf = (float*)sm;
    const int t = threadIdx.x, lane = t & 31, wid = t >> 5;
    const int bid = blockIdx.x;
    const int q = lane >> 2, qp = lane & 3;
    const int mol = wid >> 1;                 // molecule 0/1
    const int mrow = wid * 32;                // warp's global row base
    const int mloc = mrow & 63;               // 0 or 32 within molecule

    uint32_t* Whi = (uint32_t*)(sm + OFF_W);  uint32_t* Wlo = Whi + 72 * SWW;
    uint32_t* Hhi = (uint32_t*)(sm + OFF_H + mol * HTILE);
    uint16_t* H16h = (uint16_t*)(sm + OFF_H + mol * HTILE);

    // ===== phase 0: colsum partials (streams adjacency through L2) =====
    {
        const float2* Ab = (const float2*)(adj + (size_t)bid * 8192);
        float2 cs0 = make_float2(0.f, 0.f), cs1 = make_float2(0.f, 0.f);
        #pragma unroll
        for (int k = 0; k < 32; k++) {
            float2 v = __ldg(&Ab[t + 128 * k]);
            if (k < 16) { cs0.x += v.x; cs0.y += v.y; }
            else        { cs1.x += v.x; cs1.y += v.y; }
        }
        const int g = t >> 5, c0 = (t & 31) * 2;
        smf[CSP + g * 128 + c0]          = cs0.x;
        smf[CSP + g * 128 + c0 + 1]      = cs0.y;
        smf[CSP + g * 128 + 64 + c0]     = cs1.x;
        smf[CSP + g * 128 + 64 + c0 + 1] = cs1.y;
    }
    {   // W1 split tiles
        const uint4* gw = (const uint4*)g_wt[0][0];
        uint4* sw = (uint4*)(sm + OFF_W);
        #pragma unroll
        for (int i = t; i < 2 * WTILE / 16; i += 128) sw[i] = gw[i];
    }
    if (t < 72) { smf[B1I + t] = (t < 70) ? b1[t] : 0.f;
                  smf[B2I + t] = (t < 70) ? b2[t] : 0.f; }
    if (t < 11) smf[BPI + t] = bp[t];
    __syncthreads();

    // colsum reduce -> CSI (disjoint from CSP; CSP dead after this)
    smf[CSI + t] = smf[CSP + t] + smf[CSP + 128 + t]
                 + smf[CSP + 256 + t] + smf[CSP + 384 + t];

    float C0[9][4], C1[9][4];
    #pragma unroll
    for (int n = 0; n < 9; n++)
        #pragma unroll
        for (int i = 0; i < 4; i++) { C0[n][i] = 0.f; C1[n][i] = 0.f; }

    // ================= GEMM1: D1 = X @ W1^T (K=80, 3-term, dbl-buffered) ===
    {
        const int abase = bid * 128 + mrow + q;
        const float2* e00 = (const float2*)(emb + (size_t)__ldg(&atoms[abase])      * 70);
        const float2* e01 = (const float2*)(emb + (size_t)__ldg(&atoms[abase + 8])  * 70);
        const float2* e10 = (const float2*)(emb + (size_t)__ldg(&atoms[abase + 16]) * 70);
        const float2* e11 = (const float2*)(emb + (size_t)__ldg(&atoms[abase + 24]) * 70);
        const float2 z2 = make_float2(0.f, 0.f);

        float2 va[8], vb[8];
        {
            const int k0 = 2 * qp, k1 = k0 + 8;
            va[0] = __ldg(&e00[k0 >> 1]); va[1] = __ldg(&e01[k0 >> 1]);
            va[2] = __ldg(&e00[k1 >> 1]); va[3] = __ldg(&e01[k1 >> 1]);
            va[4] = __ldg(&e10[k0 >> 1]); va[5] = __ldg(&e11[k0 >> 1]);
            va[6] = __ldg(&e10[k1 >> 1]); va[7] = __ldg(&e11[k1 >> 1]);
        }
        #pragma unroll
        for (int ks = 0; ks < 5; ks++) {
            float2* cur = (ks & 1) ? vb : va;
            float2* nxt = (ks & 1) ? va : vb;
            if (ks < 4) {
                const int k0 = 16 * (ks + 1) + 2 * qp, k1 = k0 + 8;
                nxt[0] = (k0 < 70) ? __ldg(&e00[k0 >> 1]) : z2;
                nxt[1] = (k0 < 70) ? __ldg(&e01[k0 >> 1]) : z2;
                nxt[2] = (k1 < 70) ? __ldg(&e00[k1 >> 1]) : z2;
                nxt[3] = (k1 < 70) ? __ldg(&e01[k1 >> 1]) : z2;
                nxt[4] = (k0 < 70) ? __ldg(&e10[k0 >> 1]) : z2;
                nxt[5] = (k0 < 70) ? __ldg(&e11[k0 >> 1]) : z2;
                nxt[6] = (k1 < 70) ? __ldg(&e10[k1 >> 1]) : z2;
                nxt[7] = (k1 < 70) ? __ldg(&e11[k1 >> 1]) : z2;
            }
            uint32_t ah0[4], al0[4], ah1[4], al1[4];
            splitf2(cur[0], ah0[0], al0[0]);
            splitf2(cur[1], ah0[1], al0[1]);
            splitf2(cur[2], ah0[2], al0[2]);
            splitf2(cur[3], ah0[3], al0[3]);
            splitf2(cur[4], ah1[0], al1[0]);
            splitf2(cur[5], ah1[1], al1[1]);
            splitf2(cur[6], ah1[2], al1[2]);
            splitf2(cur[7], ah1[3], al1[3]);
            mma_n9x2<3>(Whi, Wlo, ks * 8 + qp, SWW, q,
                        ah0, al0, ah1, al1, C0, C1);
        }
    }

    // ---- epi1: H1 = relu(D1+b1) -> H^T (hi only) ----
    #pragma unroll
    for (int m2 = 0; m2 < 2; m2++) {
        float (*C)[4] = m2 ? C1 : C0;
        const int r0 = mloc + m2 * 16 + q, r1 = r0 + 8;
        #pragma unroll
        for (int n = 0; n < 9; n++) {
            const int d0 = n * 8 + qp * 2;
            H16h[d0 * 72 + r0]       = bf16h(fmaxf(C[n][0] + smf[B1I + d0], 0.f));
            H16h[(d0 + 1) * 72 + r0] = bf16h(fmaxf(C[n][1] + smf[B1I + d0 + 1], 0.f));
            H16h[d0 * 72 + r1]       = bf16h(fmaxf(C[n][2] + smf[B1I + d0], 0.f));
            H16h[(d0 + 1) * 72 + r1] = bf16h(fmaxf(C[n][3] + smf[B1I + d0 + 1], 0.f));
        }
    }
    __syncthreads();   // H ready; W1 consumed

    {   // W2 split tiles over W1 (completes before post-GEMM2 sync)
        const uint4* gw = (const uint4*)g_wt[1][0];
        uint4* sw = (uint4*)(sm + OFF_W);
        #pragma unroll
        for (int i = t; i < 2 * WTILE / 16; i += 128) sw[i] = gw[i];
    }

    // ====== GEMM2: D2 = A @ H1 (K=64, 1-term bf16, JIT A-frags) ============
    #pragma unroll
    for (int n = 0; n < 9; n++)
        #pragma unroll
        for (int i = 0; i < 4; i++) { C0[n][i] = 0.f; C1[n][i] = 0.f; }
    {
        const float2* A2 = (const float2*)(adj + ((size_t)(2 * bid) + mol) * 4096);
        const int rb = (mloc + q) * 32;
        float2 va[8], vb[8];
        {
            const int cp0 = qp, cp1 = qp + 4;
            va[0] = __ldg(&A2[rb + cp0]);       va[1] = __ldg(&A2[rb + 256 + cp0]);
            va[2] = __ldg(&A2[rb + cp1]);       va[3] = __ldg(&A2[rb + 256 + cp1]);
            va[4] = __ldg(&A2[rb + 512 + cp0]); va[5] = __ldg(&A2[rb + 768 + cp0]);
            va[6] = __ldg(&A2[rb + 512 + cp1]); va[7] = __ldg(&A2[rb + 768 + cp1]);
        }
        #pragma unroll
        for (int ks = 0; ks < 4; ks++) {
            float2* cur = (ks & 1) ? vb : va;
            float2* nxt = (ks & 1) ? va : vb;
            if (ks < 3) {
                const int cp0 = 8 * (ks + 1) + qp, cp1 = cp0 + 4;
                nxt[0] = __ldg(&A2[rb + cp0]);       nxt[1] = __ldg(&A2[rb + 256 + cp0]);
                nxt[2] = __ldg(&A2[rb + cp1]);       nxt[3] = __ldg(&A2[rb + 256 + cp1]);
                nxt[4] = __ldg(&A2[rb + 512 + cp0]); nxt[5] = __ldg(&A2[rb + 768 + cp0]);
                nxt[6] = __ldg(&A2[rb + 512 + cp1]); nxt[7] = __ldg(&A2[rb + 768 + cp1]);
            }
            uint32_t a0[4], a1[4];
            a0[0] = packb(cur[0]); a0[1] = packb(cur[1]);
            a0[2] = packb(cur[2]); a0[3] = packb(cur[3]);
            a1[0] = packb(cur[4]); a1[1] = packb(cur[5]);
            a1[2] = packb(cur[6]); a1[3] = packb(cur[7]);
            mma_n9x2<1>(Hhi, Hhi, ks * 8 + qp, SHW, q, a0, a0, a1, a1, C0, C1);
        }
    }
    __syncthreads();   // W2 stores complete

    // ================= GEMM3: D3 = D2 @ W2^T (chained, K=80, 3-term) =======
    float C3a[9][4], C3b[9][4];
    #pragma unroll
    for (int n = 0; n < 9; n++)
        #pragma unroll
        for (int i = 0; i < 4; i++) { C3a[n][i] = 0.f; C3b[n][i] = 0.f; }
    #pragma unroll
    for (int ks = 0; ks < 5; ks++) {
        uint32_t ah0[4], al0[4], ah1[4], al1[4];
        splitf2(make_float2(C0[2*ks][0], C0[2*ks][1]), ah0[0], al0[0]);
        splitf2(make_float2(C0[2*ks][2], C0[2*ks][3]), ah0[1], al0[1]);
        splitf2(make_float2(C1[2*ks][0], C1[2*ks][1]), ah1[0], al1[0]);
        splitf2(make_float2(C1[2*ks][2], C1[2*ks][3]), ah1[1], al1[1]);
        if (ks < 4) {
            splitf2(make_float2(C0[2*ks+1][0], C0[2*ks+1][1]), ah0[2], al0[2]);
            splitf2(make_float2(C0[2*ks+1][2], C0[2*ks+1][3]), ah0[3], al0[3]);
            splitf2(make_float2(C1[2*ks+1][0], C1[2*ks+1][1]), ah1[2], al1[2]);
            splitf2(make_float2(C1[2*ks+1][2], C1[2*ks+1][3]), ah1[3], al1[3]);
        } else {
            ah0[2] = al0[2] = ah0[3] = al0[3] = 0u;
            ah1[2] = al1[2] = ah1[3] = al1[3] = 0u;
        }
        mma_n9x2<3>(Whi, Wlo, ks * 8 + qp, SWW, q,
                    ah0, al0, ah1, al1, C3a, C3b);
    }

    // ---- epi3: pool partials y[d] += csum[r] * relu(D3[r][d]+b2[d]) ----
    {
        const float cs00 = smf[CSI + mrow + q];
        const float cs01 = smf[CSI + mrow + q + 8];
        const float cs10 = smf[CSI + mrow + q + 16];
        const float cs11 = smf[CSI + mrow + q + 24];
        #pragma unroll
        for (int n = 0; n < 9; n++) {
            #pragma unroll
            for (int j = 0; j < 2; j++) {
                const int d = n * 8 + qp * 2 + j;
                const float bb = smf[B2I + d];
                float v = cs00 * fmaxf(C3a[n][j] + bb, 0.f)
                        + cs01 * fmaxf(C3a[n][2 + j] + bb, 0.f)
                        + cs10 * fmaxf(C3b[n][j] + bb, 0.f)
                        + cs11 * fmaxf(C3b[n][2 + j] + bb, 0.f);
                v += __shfl_xor_sync(0xFFFFFFFFu, v, 4);
                v += __shfl_xor_sync(0xFFFFFFFFu, v, 8);
                v += __shfl_xor_sync(0xFFFFFFFFu, v, 16);
                if (q == 0) smf[PLI + wid * 72 + d] = v;
            }
        }
    }
    __syncthreads();

    // reduce 2 warps per molecule (144 entries, strided over 128 threads)
    for (int i = t; i < 144; i += 128) {
        const int mY = i / 72, d = i - mY * 72;
        smf[YI + i] = smf[PLI + (mY * 2 + 0) * 72 + d]
                    + smf[PLI + (mY * 2 + 1) * 72 + d];
    }
    __syncthreads();

    // head
    if (t < 22) {
        const int mH = t / 11, c = t - mH * 11;
        float s = smf[BPI + c];
        #pragma unroll 7
        for (int d = 0; d < 70; d++)
            s += smf[YI + mH * 72 + d] * __ldg(&wp[d * 11 + c]);
        const float* sv = sel + (size_t)(2 * bid + mH) * 7;
        #pragma unroll
        for (int e = 0; e < 7; e++)
            s += __ldg(&sv[e]) * __ldg(&wp[(70 + e) * 11 + c]);
        out[(size_t)(2 * bid + mH) * 11 + c] = s;
    }
}

extern "C" void kernel_launch(void* const* d_in, const int* in_sizes, int n_in,
                              void* d_out, int out_size)
{
    const int*   atoms = (const int*)  d_in[0];
    const float* adj   = (const float*)d_in[1];
    const float* sel   = (const float*)d_in[2];
    const float* emb   = (const float*)d_in[3];
    const float* w1    = (const float*)d_in[4];
    const float* b1    = (const float*)d_in[5];
    const float* w2    = (const float*)d_in[6];
    const float* b2    = (const float*)d_in[7];
    const float* wp    = (const float*)d_in[8];
    const float* bp    = (const float*)d_in[9];
    float* out = (float*)d_out;

    prep_w<<<(2 * 72 * 88 + 127) / 128, 128>>>(w1, w2);

    cudaFuncSetAttribute(pathway_mma7,
                         cudaFuncAttributeMaxDynamicSharedMemorySize, SMEM_BYTES);
    pathway_mma7<<<4096, 128, SMEM_BYTES>>>(atoms, adj, sel, emb,
                                            b1, b2, wp, bp, out);
}